// round 1
// baseline (speedup 1.0000x reference)
#include <cuda_runtime.h>
#include <math.h>

// Problem constants
#define BB   1024            // batch
#define UU   2048            // num_units
#define GK   4096            // GEMM K  (= 2U)
#define GN   8192            // GEMM N  (= 4U)
#define BM   128
#define BN   128
#define BK   32
#define NIT  (GK / BK)       // 128 k-iterations

#define LDA  136             // BM + 8  (conflict-free padding, keeps 16B align)
#define LDB  136             // BN + 8
#define ABUF (BK * LDA)      // 4352 floats per A buffer
#define BBUF (BK * LDB)      // 4352 floats per B buffer
#define SMEM_FLOATS (2 * ABUF + 2 * BBUF)       // 17408 floats
#define SMEM_BYTES  (SMEM_FLOATS * 4)           // 69632 bytes

// 32 MB scratch for pre-activation ifgo (allocation-free scratch per rules)
__device__ float g_ifgo[(size_t)BB * GN];

__device__ __forceinline__ float to_tf32(float x) {
    float r;
    asm("cvt.rna.tf32.f32 %0, %1;" : "=f"(r) : "f"(x));
    return r;
}

__device__ __forceinline__ void mma_tf32(float c[4], const unsigned a[4], const unsigned b[2]) {
    asm volatile(
        "mma.sync.aligned.m16n8k8.row.col.f32.tf32.tf32.f32 "
        "{%0,%1,%2,%3}, {%4,%5,%6,%7}, {%8,%9}, {%0,%1,%2,%3};"
        : "+f"(c[0]), "+f"(c[1]), "+f"(c[2]), "+f"(c[3])
        : "r"(a[0]), "r"(a[1]), "r"(a[2]), "r"(a[3]), "r"(b[0]), "r"(b[1]));
}

__global__ __launch_bounds__(256, 1)
void lstm_gemm_kernel(const float* __restrict__ x,
                      const float* __restrict__ h,
                      const float* __restrict__ W) {
    extern __shared__ float smem[];
    float* As = smem;                 // [2][BK][LDA]
    float* Bs = smem + 2 * ABUF;      // [2][BK][LDB]

    const int tid  = threadIdx.x;
    const int lane = tid & 31;
    const int warp = tid >> 5;

    const int rowBase = blockIdx.x * BM;     // batch-tile base (row-fastest for W L2 reuse)
    const int colBase = blockIdx.y * BN;     // output-column tile base
    const int nIdx  = colBase >> 12;         // which n-split (0/1)
    const int fBase = colBase & 4095;        // column inside that split

    // A-load mapping: thread -> (row a_b, 16-wide k-half)
    const int a_b    = tid & 127;
    const int a_half = tid >> 7;             // 0/1 -> k offset 0/16
    // B-load mapping: thread -> (f4 column, base d row)
    const int b_f4 = (tid & 31) * 4;
    const int b_d0 = tid >> 5;               // 0..7, stride 8 over 32 d-rows

    // Warp tile: 2 warps along M (64 each), 4 along N (32 each)
    const int wm = (warp & 1) * 64;
    const int wn = (warp >> 1) * 32;
    const int g  = lane >> 2;                // groupID
    const int q  = lane & 3;                 // thread-in-group

    float acc[4][4][4];
    #pragma unroll
    for (int mi = 0; mi < 4; ++mi)
        #pragma unroll
        for (int ni = 0; ni < 4; ++ni)
            #pragma unroll
            for (int r = 0; r < 4; ++r) acc[mi][ni][r] = 0.f;

    float4 aReg[4], bReg[4];

    // ---- global-load helper (inlined via macro to avoid lambda quirks) ----
    #define LOAD_G(IT) do {                                                         \
        const int kkBase = (IT) * BK;                                               \
        const int ksp = kkBase >> 11;          /* k-split 0/1 */                    \
        const int d0  = kkBase & 2047;                                              \
        const float* asrc = (d0 < 1024)                                             \
            ? (x + (size_t)ksp * 1024 + d0)                                         \
            : (h + (size_t)ksp * 1024 + (d0 - 1024));                               \
        const float* arow = asrc + (size_t)(rowBase + a_b) * UU;                    \
        _Pragma("unroll")                                                           \
        for (int j = 0; j < 4; ++j)                                                 \
            aReg[j] = *reinterpret_cast<const float4*>(arow + a_half * 16 + j * 4); \
        const float* bsrc = W + ((size_t)(ksp * 2 + nIdx) * 2048 + d0) * 4096 + fBase; \
        _Pragma("unroll")                                                           \
        for (int j = 0; j < 4; ++j)                                                 \
            bReg[j] = *reinterpret_cast<const float4*>(bsrc + (size_t)(b_d0 + 8 * j) * 4096 + b_f4); \
    } while (0)

    #define STORE_S(BUFI) do {                                                      \
        float* Ab = As + (BUFI) * ABUF;                                             \
        float* Bb = Bs + (BUFI) * BBUF;                                             \
        _Pragma("unroll")                                                           \
        for (int j = 0; j < 4; ++j) {                                               \
            const int kk = a_half * 16 + j * 4;                                     \
            Ab[(kk + 0) * LDA + a_b] = to_tf32(aReg[j].x);                          \
            Ab[(kk + 1) * LDA + a_b] = to_tf32(aReg[j].y);                          \
            Ab[(kk + 2) * LDA + a_b] = to_tf32(aReg[j].z);                          \
            Ab[(kk + 3) * LDA + a_b] = to_tf32(aReg[j].w);                          \
        }                                                                           \
        _Pragma("unroll")                                                           \
        for (int j = 0; j < 4; ++j) {                                               \
            float4 v;                                                               \
            v.x = to_tf32(bReg[j].x); v.y = to_tf32(bReg[j].y);                     \
            v.z = to_tf32(bReg[j].z); v.w = to_tf32(bReg[j].w);                     \
            *reinterpret_cast<float4*>(Bb + (b_d0 + 8 * j) * LDB + b_f4) = v;       \
        }                                                                           \
    } while (0)

    LOAD_G(0);
    STORE_S(0);
    __syncthreads();

    for (int it = 0; it < NIT; ++it) {
        if (it + 1 < NIT) LOAD_G(it + 1);

        // ---- compute from buffer (it & 1) ----
        {
            const float* Ab = As + (it & 1) * ABUF;
            const float* Bb = Bs + (it & 1) * BBUF;
            #pragma unroll
            for (int s = 0; s < 4; ++s) {
                const int k0 = s * 8 + q;
                unsigned afr[4][4], bfr[4][2];
                #pragma unroll
                for (int mi = 0; mi < 4; ++mi) {
                    const int r = wm + mi * 16 + g;
                    afr[mi][0] = __float_as_uint(Ab[k0 * LDA + r]);
                    afr[mi][1] = __float_as_uint(Ab[k0 * LDA + r + 8]);
                    afr[mi][2] = __float_as_uint(Ab[(k0 + 4) * LDA + r]);
                    afr[mi][3] = __float_as_uint(Ab[(k0 + 4) * LDA + r + 8]);
                }
                #pragma unroll
                for (int ni = 0; ni < 4; ++ni) {
                    const int cc = wn + ni * 8 + g;
                    bfr[ni][0] = __float_as_uint(Bb[k0 * LDB + cc]);
                    bfr[ni][1] = __float_as_uint(Bb[(k0 + 4) * LDB + cc]);
                }
                #pragma unroll
                for (int mi = 0; mi < 4; ++mi)
                    #pragma unroll
                    for (int ni = 0; ni < 4; ++ni)
                        mma_tf32(acc[mi][ni], afr[mi], bfr[ni]);
            }
        }

        if (it + 1 < NIT) STORE_S((it + 1) & 1);
        __syncthreads();
    }

    // ---- write pre-activation ifgo to scratch ----
    #pragma unroll
    for (int mi = 0; mi < 4; ++mi) {
        const int r0 = rowBase + wm + mi * 16 + g;
        #pragma unroll
        for (int ni = 0; ni < 4; ++ni) {
            const int c0 = colBase + wn + ni * 8 + q * 2;
            float2 v0 = make_float2(acc[mi][ni][0], acc[mi][ni][1]);
            float2 v1 = make_float2(acc[mi][ni][2], acc[mi][ni][3]);
            *reinterpret_cast<float2*>(&g_ifgo[(size_t)r0 * GN + c0])       = v0;
            *reinterpret_cast<float2*>(&g_ifgo[(size_t)(r0 + 8) * GN + c0]) = v1;
        }
    }
    #undef LOAD_G
    #undef STORE_S
}

__global__ void lstm_gate_kernel(const float* __restrict__ c, float* __restrict__ out) {
    const int e = blockIdx.x * blockDim.x + threadIdx.x;  // 0 .. B*U-1
    if (e >= BB * UU) return;
    const int b  = e >> 11;      // / 2048
    const int u  = e & 2047;
    const int n  = u >> 10;      // n-split
    const int uu = u & 1023;
    const size_t base = (size_t)b * GN + (size_t)n * 4096 + uu;
    const float iv = g_ifgo[base];
    const float fv = g_ifgo[base + 1024];
    const float gv = g_ifgo[base + 2048];
    const float ov = g_ifgo[base + 3072];
    const float ig = 1.f / (1.f + expf(-iv));
    const float fg = 1.f / (1.f + expf(-fv));
    const float og = 1.f / (1.f + expf(-ov));
    const float gg = tanhf(gv);
    const float cin = c[e];
    const float nc = fg * cin + ig * gg;
    const float nh = og * tanhf(nc);
    out[e] = nh;                          // new_h  [B, U]
    out[(size_t)BB * UU + e] = nc;        // new_c  [B, U]
}

extern "C" void kernel_launch(void* const* d_in, const int* in_sizes, int n_in,
                              void* d_out, int out_size) {
    const float* x = (const float*)d_in[0];
    const float* h = (const float*)d_in[1];
    const float* c = (const float*)d_in[2];
    const float* W = (const float*)d_in[3];
    float* out = (float*)d_out;

    cudaFuncSetAttribute(lstm_gemm_kernel,
                         cudaFuncAttributeMaxDynamicSharedMemorySize, SMEM_BYTES);

    // Grid: x = row(batch) tiles FASTEST so the 8 blocks sharing one W column
    // panel are co-resident -> W read ~once from HBM, rest from L2.
    lstm_gemm_kernel<<<dim3(8, 64), 256, SMEM_BYTES>>>(x, h, W);
    lstm_gate_kernel<<<(BB * UU) / 256, 256>>>(c, out);
}

// round 3
// speedup vs baseline: 6.6300x; 6.6300x over previous
#include <cuda_runtime.h>
#include <cuda_fp16.h>
#include <cstdint>
#include <math.h>

// ---------------- problem constants ----------------
#define BB   1024
#define UU   2048
#define GK   4096            // GEMM K = 2U
#define GN   8192            // GEMM N = 4U

// ---------------- arch gate: tcgen05 only exists on '-a' targets ----------------
#if defined(__CUDA_ARCH__) && (defined(__CUDA_ARCH_FEAT_SM103_ALL) || \
                               defined(__CUDA_ARCH_FEAT_SM100_ALL) || \
                               defined(__CUDA_ARCH_FEAT_SM101_ALL))
#define HAS_TCGEN05 1
#else
#define HAS_TCGEN05 0
#endif

// ---------------- tcgen05 GEMM tiling ----------------
#define BM   256             // CTA M tile (2 x 128 MMA subtiles)
#define BN   256             // CTA N tile (2 x 128 MMA halves)
#define BK   64              // k-chunk (64 fp16 = 128B rows -> SW128)
#define NC   (GK / BK)       // 64 chunks
#define NSTAGE 3

#define SMEM_TMEM_PTR 0
#define SMEM_MBAR0    8
#define SMEM_MBAR1    16
#define SMEM_STAGE0   1024
#define STAGE_BYTES   65536           // A 32KB + B 32KB
#define STAGE_B_OFF   32768
#define SMEM_BYTES    (1024 + NSTAGE * STAGE_BYTES)   // 197632 (covers fallback's 69632 too)

// idesc kind::f16: F32 accum (1<<4), atype=btype=F16 (0), N=128 (16<<17), M=128 (8<<24)
#define MMA_IDESC  ((1u << 4) | (16u << 17) | (8u << 24))

// ---------------- device scratch (allocation-free) ----------------
__device__ __half g_Af16[(size_t)BB * GK];        // [1024][4096] packed xh, fp16
__device__ __half g_Wt  [(size_t)GN * GK];        // [8192][4096] W transposed, fp16 K-major
__device__ float  g_ifgo[(size_t)BB * GN];        // pre-activation GEMM output

// ---------------- generic helpers ----------------
__device__ __forceinline__ uint32_t smem_u32(const void* p) {
    uint32_t a;
    asm("{ .reg .u64 t; cvta.to.shared.u64 t, %1; cvt.u32.u64 %0, t; }" : "=r"(a) : "l"(p));
    return a;
}
#define SW128(off) ((off) ^ (((off) >> 3) & 0x70))

// ================= preprocessing (arch-independent) =================

__global__ void pack_a_kernel(const float* __restrict__ x, const float* __restrict__ h) {
    const int gi = blockIdx.x * blockDim.x + threadIdx.x;   // float4 group
    const int b  = gi >> 10;
    const int k  = (gi & 1023) * 4;
    const int ksp = k >> 11;
    const int d   = k & 2047;
    const float* src = (d < 1024) ? (x + (size_t)b * UU + ksp * 1024 + d)
                                  : (h + (size_t)b * UU + ksp * 1024 + (d - 1024));
    const float4 v = *reinterpret_cast<const float4*>(src);
    __half2 p0 = __floats2half2_rn(v.x, v.y);
    __half2 p1 = __floats2half2_rn(v.z, v.w);
    uint2 o;
    o.x = *reinterpret_cast<uint32_t*>(&p0);
    o.y = *reinterpret_cast<uint32_t*>(&p1);
    *reinterpret_cast<uint2*>(&g_Af16[(size_t)b * GK + k]) = o;
}

__global__ void transpose_w_kernel(const float* __restrict__ W) {
    __shared__ float tile[32][33];
    const int ksp = blockIdx.z >> 1, nsp = blockIdx.z & 1;
    const int dBase = blockIdx.y * 32, fBase = blockIdx.x * 32;
    const float* src = W + ((size_t)(ksp * 2 + nsp) * 2048 + dBase) * 4096 + fBase;
    #pragma unroll
    for (int j = 0; j < 4; ++j) {
        const int r = threadIdx.y * 4 + j;
        tile[r][threadIdx.x] = src[(size_t)r * 4096 + threadIdx.x];
    }
    __syncthreads();
    __half* dst = g_Wt + ((size_t)(nsp * 4096 + fBase)) * GK + ksp * 2048 + dBase;
    #pragma unroll
    for (int j = 0; j < 4; ++j) {
        const int r = threadIdx.y * 4 + j;   // n within tile
        dst[(size_t)r * GK + threadIdx.x] = __float2half_rn(tile[threadIdx.x][r]);
    }
}

// ================= arch-specific helpers =================
#if HAS_TCGEN05
__device__ __forceinline__ uint32_t elect_one() {
    uint32_t pred;
    asm volatile("{\n\t.reg .pred p;\n\telect.sync _|p, 0xFFFFFFFF;\n\t"
                 "selp.b32 %0, 1, 0, p;\n\t}" : "=r"(pred));
    return pred;
}
// SW128 K-major smem descriptor: layout=2, version=1, SBO=64, LBO=1
#define DESC_BASE ((uint64_t(2) << 61) | (uint64_t(1) << 46) | (uint64_t(64) << 32) | (uint64_t(1) << 16))
#define MK_DESC(addr) (DESC_BASE | ((uint64_t)((addr) >> 4) & 0x3FFF))

__device__ __forceinline__ void mma_f16_ss(uint32_t d, uint64_t ad, uint64_t bd,
                                           uint32_t idesc, uint32_t en) {
    asm volatile(
        "{\n\t.reg .pred p;\n\tsetp.ne.u32 p, %4, 0;\n\t"
        "tcgen05.mma.cta_group::1.kind::f16 [%0], %1, %2, %3, {%5,%5,%5,%5}, p;\n\t}"
        :: "r"(d), "l"(ad), "l"(bd), "r"(idesc), "r"(en), "r"(0u) : "memory");
}
#define MBAR_INIT(a, c)  asm volatile("mbarrier.init.shared.b64 [%0], %1;" :: "r"(a), "r"(c) : "memory")
#define MBAR_INVAL(a)    asm volatile("mbarrier.inval.shared.b64 [%0];" :: "r"(a) : "memory")
#define TC_COMMIT(a)     asm volatile("tcgen05.commit.cta_group::1.mbarrier::arrive::one.shared::cluster.b64 [%0];" :: "r"(a) : "memory")
#define TC_ALLOC(sa, n)  asm volatile("tcgen05.alloc.cta_group::1.sync.aligned.shared::cta.b32 [%0], %1;" :: "r"(sa), "r"(n) : "memory")
#define TC_DEALLOC(t, n) asm volatile("tcgen05.dealloc.cta_group::1.sync.aligned.b32 %0, %1;" :: "r"(t), "r"(n))
#define TC_RELINQ()      asm volatile("tcgen05.relinquish_alloc_permit.cta_group::1.sync.aligned;")
#define TC_FENCE_AFTER() asm volatile("tcgen05.fence::after_thread_sync;" ::: "memory")
#define TC_WAIT_LD()     asm volatile("tcgen05.wait::ld.sync.aligned;" ::: "memory")
#define FENCE_ASYNC()    asm volatile("fence.proxy.async.shared::cta;" ::: "memory")

__device__ __forceinline__ void mbar_wait(uint32_t mbar, uint32_t parity) {
    asm volatile(
        "{\n\t.reg .pred P;\n\t"
        "W%=:\n\t"
        "mbarrier.try_wait.parity.acquire.cta.shared::cta.b64 P, [%0], %1, 0x989680;\n\t"
        "@P bra.uni D%=;\n\t"
        "bra.uni W%=;\n\t"
        "D%=:\n\t}"
        :: "r"(mbar), "r"(parity) : "memory");
}
__device__ __forceinline__ void cp16(uint32_t saddr, const void* g) {
    asm volatile("cp.async.cg.shared.global [%0], [%1], 16;" :: "r"(saddr), "l"(g) : "memory");
}
#define CP_COMMIT() asm volatile("cp.async.commit_group;" ::: "memory")

__device__ __forceinline__ void ldtm32(uint32_t* r, uint32_t addr) {
    asm volatile(
        "tcgen05.ld.sync.aligned.32x32b.x32.b32 "
        "{%0,%1,%2,%3,%4,%5,%6,%7,%8,%9,%10,%11,%12,%13,%14,%15,"
        "%16,%17,%18,%19,%20,%21,%22,%23,%24,%25,%26,%27,%28,%29,%30,%31}, [%32];"
        : "=r"(r[0]), "=r"(r[1]), "=r"(r[2]), "=r"(r[3]), "=r"(r[4]), "=r"(r[5]), "=r"(r[6]), "=r"(r[7]),
          "=r"(r[8]), "=r"(r[9]), "=r"(r[10]), "=r"(r[11]), "=r"(r[12]), "=r"(r[13]), "=r"(r[14]), "=r"(r[15]),
          "=r"(r[16]), "=r"(r[17]), "=r"(r[18]), "=r"(r[19]), "=r"(r[20]), "=r"(r[21]), "=r"(r[22]), "=r"(r[23]),
          "=r"(r[24]), "=r"(r[25]), "=r"(r[26]), "=r"(r[27]), "=r"(r[28]), "=r"(r[29]), "=r"(r[30]), "=r"(r[31])
        : "r"(addr));
}
#else
// ---- tf32 mma.sync fallback helpers (baseline arch) ----
__device__ __forceinline__ float to_tf32(float x) {
    float r;
    asm("cvt.rna.tf32.f32 %0, %1;" : "=f"(r) : "f"(x));
    return r;
}
__device__ __forceinline__ void mma_tf32(float c[4], const unsigned a[4], const unsigned b[2]) {
    asm volatile(
        "mma.sync.aligned.m16n8k8.row.col.f32.tf32.tf32.f32 "
        "{%0,%1,%2,%3}, {%4,%5,%6,%7}, {%8,%9}, {%0,%1,%2,%3};"
        : "+f"(c[0]), "+f"(c[1]), "+f"(c[2]), "+f"(c[3])
        : "r"(a[0]), "r"(a[1]), "r"(a[2]), "r"(a[3]), "r"(b[0]), "r"(b[1]));
}
#define F_LDA  136
#define F_ABUF (32 * F_LDA)
#endif

// ================= GEMM kernel: grid(4,32) x 256 threads, SMEM_BYTES dyn smem =================
__global__ __launch_bounds__(256, 1)
void lstm_gemm_tc(const float* __restrict__ x, const float* __restrict__ h,
                  const float* __restrict__ W) {
    extern __shared__ char smem_raw[];
#if HAS_TCGEN05
    const uint32_t sbase = smem_u32(smem_raw);
    const int tid  = threadIdx.x;
    const int warp = tid >> 5;
    const int lane = tid & 31;

    const int rowBase = blockIdx.x * BM;
    const int colBase = blockIdx.y * BN;

    if (warp == 0) { TC_ALLOC(sbase + SMEM_TMEM_PTR, 512); }
    else           { TC_RELINQ(); }
    __syncthreads();
    uint32_t tmem_base;
    asm volatile("ld.shared.b32 %0, [%1];" : "=r"(tmem_base) : "r"(sbase + SMEM_TMEM_PTR));

    if (tid == 0) { MBAR_INIT(sbase + SMEM_MBAR0, 1); MBAR_INIT(sbase + SMEM_MBAR1, 1); }
    __syncthreads();

    const __half* Aglob = g_Af16 + (size_t)rowBase * GK;
    const __half* Bglob = g_Wt   + (size_t)colBase * GK;

    #define LOAD_CHUNK(CH) do {                                                        \
        const int kOff = (CH) * BK;                                                    \
        const uint32_t stA = sbase + SMEM_STAGE0 + ((CH) % NSTAGE) * STAGE_BYTES;      \
        const uint32_t stB = stA + STAGE_B_OFF;                                        \
        _Pragma("unroll")                                                              \
        for (int j = 0; j < 8; ++j) {                                                  \
            const int idx = tid + 256 * j;                                             \
            const int row = idx >> 3, kg = idx & 7;                                    \
            const uint32_t so = SW128((uint32_t)(row * 128 + kg * 16));                \
            cp16(stA + so, Aglob + (size_t)row * GK + kOff + kg * 8);                  \
        }                                                                              \
        _Pragma("unroll")                                                              \
        for (int j = 0; j < 8; ++j) {                                                  \
            const int idx = tid + 256 * j;                                             \
            const int row = idx >> 3, kg = idx & 7;                                    \
            const uint32_t so = SW128((uint32_t)(row * 128 + kg * 16));                \
            cp16(stB + so, Bglob + (size_t)row * GK + kOff + kg * 8);                  \
        }                                                                              \
        CP_COMMIT();                                                                   \
    } while (0)

    LOAD_CHUNK(0);
    LOAD_CHUNK(1);

    for (int it = 0; it < NC; ++it) {
        if (it == NC - 1) { asm volatile("cp.async.wait_group 0;" ::: "memory"); }
        else              { asm volatile("cp.async.wait_group 1;" ::: "memory"); }
        __syncthreads();

        if (warp == 0 && elect_one()) {
            FENCE_ASYNC();
            const uint32_t st = sbase + SMEM_STAGE0 + (it % NSTAGE) * STAGE_BYTES;
            const uint64_t aD = MK_DESC(st);
            const uint64_t bD = MK_DESC(st + STAGE_B_OFF);
            #pragma unroll
            for (int m = 0; m < 2; ++m)
                #pragma unroll
                for (int hh = 0; hh < 2; ++hh) {
                    const uint32_t dcol = tmem_base + m * 256 + hh * 128;
                    #pragma unroll
                    for (int ks = 0; ks < 4; ++ks)
                        mma_f16_ss(dcol, aD + m * 1024 + ks * 2, bD + hh * 1024 + ks * 2,
                                   MMA_IDESC, (uint32_t)(it > 0 || ks > 0));
                }
            TC_COMMIT(sbase + ((it & 1) ? SMEM_MBAR1 : SMEM_MBAR0));
        }

        if (it + 2 < NC) {
            if (it >= 1) {
                const int cc = it - 1;
                mbar_wait(sbase + ((cc & 1) ? SMEM_MBAR1 : SMEM_MBAR0), (uint32_t)((cc >> 1) & 1));
            }
            LOAD_CHUNK(it + 2);
        }
    }
    #undef LOAD_CHUNK

    {
        const int cc = NC - 1;
        mbar_wait(sbase + ((cc & 1) ? SMEM_MBAR1 : SMEM_MBAR0), (uint32_t)((cc >> 1) & 1));
    }
    TC_FENCE_AFTER();

    {
        const int m   = warp >> 2;
        const int sub = warp & 3;
        const int row_g = rowBase + m * 128 + sub * 32 + lane;
        float* dstRow = &g_ifgo[(size_t)row_g * GN + colBase];
        uint32_t regs[32];
        #pragma unroll
        for (int cb = 0; cb < 8; ++cb) {
            ldtm32(regs, tmem_base + m * 256 + cb * 32);
            TC_WAIT_LD();
            #pragma unroll
            for (int j = 0; j < 8; ++j) {
                float4 v;
                v.x = __uint_as_float(regs[j * 4 + 0]);
                v.y = __uint_as_float(regs[j * 4 + 1]);
                v.z = __uint_as_float(regs[j * 4 + 2]);
                v.w = __uint_as_float(regs[j * 4 + 3]);
                *reinterpret_cast<float4*>(dstRow + cb * 32 + j * 4) = v;
            }
        }
    }

    __syncthreads();
    if (tid == 0) { MBAR_INVAL(sbase + SMEM_MBAR0); MBAR_INVAL(sbase + SMEM_MBAR1); }
    __syncthreads();
    if (warp == 0) { TC_DEALLOC(tmem_base, 512); }

#else  // ===================== tf32 mma.sync fallback (proven R1 body) =====================
    float* As = reinterpret_cast<float*>(smem_raw);           // [2][32][F_LDA]
    float* Bs = As + 2 * F_ABUF;                              // [2][32][F_LDA]

    const int tid  = threadIdx.x;
    const int lane = tid & 31;
    const int warp = tid >> 5;

    const int a_b    = tid & 127;
    const int a_half = tid >> 7;
    const int b_f4 = (tid & 31) * 4;
    const int b_d0 = tid >> 5;

    const int wm = (warp & 1) * 64;
    const int wn = (warp >> 1) * 32;
    const int g  = lane >> 2;
    const int q  = lane & 3;

    for (int s = 0; s < 4; ++s) {
        const int rowBase = (blockIdx.x * 2 + (s & 1)) * 128;
        const int colBase = (blockIdx.y * 2 + (s >> 1)) * 128;
        const int nIdx  = colBase >> 12;
        const int fBase = colBase & 4095;

        float acc[4][4][4];
        #pragma unroll
        for (int mi = 0; mi < 4; ++mi)
            #pragma unroll
            for (int ni = 0; ni < 4; ++ni)
                #pragma unroll
                for (int r = 0; r < 4; ++r) acc[mi][ni][r] = 0.f;

        float4 aReg[4], bReg[4];

        #define LOAD_G(IT) do {                                                         \
            const int kkBase = (IT) * 32;                                               \
            const int ksp = kkBase >> 11;                                               \
            const int d0  = kkBase & 2047;                                              \
            const float* asrc = (d0 < 1024)                                             \
                ? (x + (size_t)ksp * 1024 + d0)                                         \
                : (h + (size_t)ksp * 1024 + (d0 - 1024));                               \
            const float* arow = asrc + (size_t)(rowBase + a_b) * UU;                    \
            _Pragma("unroll")                                                           \
            for (int j = 0; j < 4; ++j)                                                 \
                aReg[j] = *reinterpret_cast<const float4*>(arow + a_half * 16 + j * 4); \
            const float* bsrc = W + ((size_t)(ksp * 2 + nIdx) * 2048 + d0) * 4096 + fBase; \
            _Pragma("unroll")                                                           \
            for (int j = 0; j < 4; ++j)                                                 \
                bReg[j] = *reinterpret_cast<const float4*>(bsrc + (size_t)(b_d0 + 8 * j) * 4096 + b_f4); \
        } while (0)

        #define STORE_S(BUFI) do {                                                      \
            float* Ab = As + (BUFI) * F_ABUF;                                           \
            float* Bb = Bs + (BUFI) * F_ABUF;                                           \
            _Pragma("unroll")                                                           \
            for (int j = 0; j < 4; ++j) {                                               \
                const int kk = a_half * 16 + j * 4;                                     \
                Ab[(kk + 0) * F_LDA + a_b] = to_tf32(aReg[j].x);                        \
                Ab[(kk + 1) * F_LDA + a_b] = to_tf32(aReg[j].y);                        \
                Ab[(kk + 2) * F_LDA + a_b] = to_tf32(aReg[j].z);                        \
                Ab[(kk + 3) * F_LDA + a_b] = to_tf32(aReg[j].w);                        \
            }                                                                           \
            _Pragma("unroll")                                                           \
            for (int j = 0; j < 4; ++j) {                                               \
                float4 v;                                                               \
                v.x = to_tf32(bReg[j].x); v.y = to_tf32(bReg[j].y);                     \
                v.z = to_tf32(bReg[j].z); v.w = to_tf32(bReg[j].w);                     \
                *reinterpret_cast<float4*>(Bb + (b_d0 + 8 * j) * F_LDA + b_f4) = v;     \
            }                                                                           \
        } while (0)

        LOAD_G(0);
        STORE_S(0);
        __syncthreads();

        for (int it = 0; it < 128; ++it) {
            if (it + 1 < 128) LOAD_G(it + 1);
            {
                const float* Ab = As + (it & 1) * F_ABUF;
                const float* Bb = Bs + (it & 1) * F_ABUF;
                #pragma unroll
                for (int ss = 0; ss < 4; ++ss) {
                    const int k0 = ss * 8 + q;
                    unsigned afr[4][4], bfr[4][2];
                    #pragma unroll
                    for (int mi = 0; mi < 4; ++mi) {
                        const int r = wm + mi * 16 + g;
                        afr[mi][0] = __float_as_uint(Ab[k0 * F_LDA + r]);
                        afr[mi][1] = __float_as_uint(Ab[k0 * F_LDA + r + 8]);
                        afr[mi][2] = __float_as_uint(Ab[(k0 + 4) * F_LDA + r]);
                        afr[mi][3] = __float_as_uint(Ab[(k0 + 4) * F_LDA + r + 8]);
                    }
                    #pragma unroll
                    for (int ni = 0; ni < 4; ++ni) {
                        const int cc = wn + ni * 8 + g;
                        bfr[ni][0] = __float_as_uint(Bb[k0 * F_LDA + cc]);
                        bfr[ni][1] = __float_as_uint(Bb[(k0 + 4) * F_LDA + cc]);
                    }
                    #pragma unroll
                    for (int mi = 0; mi < 4; ++mi)
                        #pragma unroll
                        for (int ni = 0; ni < 4; ++ni)
                            mma_tf32(acc[mi][ni], afr[mi], bfr[ni]);
                }
            }
            if (it + 1 < 128) STORE_S((it + 1) & 1);
            __syncthreads();
        }

        #pragma unroll
        for (int mi = 0; mi < 4; ++mi) {
            const int r0 = rowBase + wm + mi * 16 + g;
            #pragma unroll
            for (int ni = 0; ni < 4; ++ni) {
                const int c0 = colBase + wn + ni * 8 + q * 2;
                float2 v0 = make_float2(acc[mi][ni][0], acc[mi][ni][1]);
                float2 v1 = make_float2(acc[mi][ni][2], acc[mi][ni][3]);
                *reinterpret_cast<float2*>(&g_ifgo[(size_t)r0 * GN + c0])       = v0;
                *reinterpret_cast<float2*>(&g_ifgo[(size_t)(r0 + 8) * GN + c0]) = v1;
            }
        }
        #undef LOAD_G
        #undef STORE_S
        __syncthreads();
    }
#endif
}

// ================= gate fusion =================
__global__ void lstm_gate_kernel(const float* __restrict__ c, float* __restrict__ out) {
    const int e = blockIdx.x * blockDim.x + threadIdx.x;
    if (e >= BB * UU) return;
    const int b  = e >> 11;
    const int u  = e & 2047;
    const int n  = u >> 10;
    const int uu = u & 1023;
    const size_t base = (size_t)b * GN + (size_t)n * 4096 + uu;
    const float iv = g_ifgo[base];
    const float fv = g_ifgo[base + 1024];
    const float gv = g_ifgo[base + 2048];
    const float ov = g_ifgo[base + 3072];
    const float ig = 1.f / (1.f + expf(-iv));
    const float fg = 1.f / (1.f + expf(-fv));
    const float og = 1.f / (1.f + expf(-ov));
    const float gg = tanhf(gv);
    const float cin = c[e];
    const float nc = fg * cin + ig * gg;
    const float nh = og * tanhf(nc);
    out[e] = nh;
    out[(size_t)BB * UU + e] = nc;
}

// ================= launch =================
extern "C" void kernel_launch(void* const* d_in, const int* in_sizes, int n_in,
                              void* d_out, int out_size) {
    const float* x = (const float*)d_in[0];
    const float* h = (const float*)d_in[1];
    const float* c = (const float*)d_in[2];
    const float* W = (const float*)d_in[3];
    float* out = (float*)d_out;

    cudaFuncSetAttribute(lstm_gemm_tc, cudaFuncAttributeMaxDynamicSharedMemorySize, SMEM_BYTES);

    pack_a_kernel<<<(BB * GK / 4) / 256, 256>>>(x, h);
    transpose_w_kernel<<<dim3(4096 / 32, 2048 / 32, 4), dim3(32, 8)>>>(W);
    lstm_gemm_tc<<<dim3(4, 32), 256, SMEM_BYTES>>>(x, h, W);
    lstm_gate_kernel<<<(BB * UU) / 256, 256>>>(c, out);
}

// round 4
// speedup vs baseline: 7.0392x; 1.0617x over previous
#include <cuda_runtime.h>
#include <cuda_fp16.h>
#include <cstdint>
#include <math.h>

// ---------------- problem constants ----------------
#define BB   1024
#define UU   2048
#define GK   4096            // GEMM K = 2U
#define GN   8192            // GEMM N = 4U

// ---------------- arch gate: tcgen05 only exists on '-a' targets ----------------
#if defined(__CUDA_ARCH__) && (defined(__CUDA_ARCH_FEAT_SM103_ALL) || \
                               defined(__CUDA_ARCH_FEAT_SM100_ALL) || \
                               defined(__CUDA_ARCH_FEAT_SM101_ALL))
#define HAS_TCGEN05 1
#else
#define HAS_TCGEN05 0
#endif

// ---------------- tcgen05 GEMM tiling ----------------
#define BM   256             // CTA M tile (2 x 128 MMA subtiles)
#define BN   256             // CTA N tile (2 x 128 MMA halves) = 64 units x 4 gates
#define BK   64              // k-chunk (64 fp16 = 128B rows -> SW128)
#define NC   (GK / BK)       // 64 chunks
#define NSTAGE 3

#define SMEM_TMEM_PTR 0
#define SMEM_MBAR0    8
#define SMEM_MBAR1    16
#define SMEM_STAGE0   1024
#define STAGE_BYTES   65536           // A 32KB + B 32KB
#define STAGE_B_OFF   32768
#define SMEM_BYTES    (1024 + NSTAGE * STAGE_BYTES)   // 197632

// idesc kind::f16: F32 accum (1<<4), atype=btype=F16 (0), N=128 (16<<17), M=128 (8<<24)
#define MMA_IDESC  ((1u << 4) | (16u << 17) | (8u << 24))

// ---------------- device scratch (allocation-free) ----------------
__device__ __half g_Af16[(size_t)BB * GK];        // [1024][4096] packed xh, fp16
__device__ __half g_Wt  [(size_t)GN * GK];        // [8192][4096] fp16 K-major, GATE-PERMUTED:
                                                  //   col n' = nsp*4096 + uu*4 + gate

// ---------------- generic helpers ----------------
__device__ __forceinline__ uint32_t smem_u32(const void* p) {
    uint32_t a;
    asm("{ .reg .u64 t; cvta.to.shared.u64 t, %1; cvt.u32.u64 %0, t; }" : "=r"(a) : "l"(p));
    return a;
}
#define SW128(off) ((off) ^ (((off) >> 3) & 0x70))

__device__ __forceinline__ float sigmoidf_(float v) { return 1.f / (1.f + expf(-v)); }

// ================= preprocessing (arch-independent) =================

__global__ void pack_a_kernel(const float* __restrict__ x, const float* __restrict__ h) {
    const int gi = blockIdx.x * blockDim.x + threadIdx.x;   // float4 group
    const int b  = gi >> 10;
    const int k  = (gi & 1023) * 4;
    const int ksp = k >> 11;
    const int d   = k & 2047;
    const float* src = (d < 1024) ? (x + (size_t)b * UU + ksp * 1024 + d)
                                  : (h + (size_t)b * UU + ksp * 1024 + (d - 1024));
    const float4 v = *reinterpret_cast<const float4*>(src);
    __half2 p0 = __floats2half2_rn(v.x, v.y);
    __half2 p1 = __floats2half2_rn(v.z, v.w);
    uint2 o;
    o.x = *reinterpret_cast<uint32_t*>(&p0);
    o.y = *reinterpret_cast<uint32_t*>(&p1);
    *reinterpret_cast<uint2*>(&g_Af16[(size_t)b * GK + k]) = o;
}

// transpose + convert + GATE-PERMUTE:
// W [ksp][nsp][d(2048)][f(4096)] fp32  ->  Wt[n'][k] fp16
//   f = gate*1024 + uu   maps to   n' = nsp*4096 + uu*4 + gate
__global__ void transpose_w_kernel(const float* __restrict__ W) {
    __shared__ float tile[32][33];
    const int ksp = blockIdx.z >> 1, nsp = blockIdx.z & 1;
    const int dBase = blockIdx.y * 32, fBase = blockIdx.x * 32;
    const float* src = W + ((size_t)(ksp * 2 + nsp) * 2048 + dBase) * 4096 + fBase;
    #pragma unroll
    for (int j = 0; j < 4; ++j) {
        const int r = threadIdx.y * 4 + j;
        tile[r][threadIdx.x] = src[(size_t)r * 4096 + threadIdx.x];
    }
    __syncthreads();
    const int gate = fBase >> 10;          // all 32 f in this block share one gate
    const int uu0  = fBase & 1023;
    #pragma unroll
    for (int j = 0; j < 4; ++j) {
        const int r = threadIdx.y * 4 + j;                 // f offset in block
        const int np = nsp * 4096 + (uu0 + r) * 4 + gate;  // permuted column
        g_Wt[(size_t)np * GK + ksp * 2048 + dBase + threadIdx.x] =
            __float2half_rn(tile[threadIdx.x][r]);
    }
}

// ================= arch-specific helpers =================
#if HAS_TCGEN05
__device__ __forceinline__ uint32_t elect_one() {
    uint32_t pred;
    asm volatile("{\n\t.reg .pred p;\n\telect.sync _|p, 0xFFFFFFFF;\n\t"
                 "selp.b32 %0, 1, 0, p;\n\t}" : "=r"(pred));
    return pred;
}
// SW128 K-major smem descriptor: layout=2, version=1, SBO=64, LBO=1
#define DESC_BASE ((uint64_t(2) << 61) | (uint64_t(1) << 46) | (uint64_t(64) << 32) | (uint64_t(1) << 16))
#define MK_DESC(addr) (DESC_BASE | ((uint64_t)((addr) >> 4) & 0x3FFF))

__device__ __forceinline__ void mma_f16_ss(uint32_t d, uint64_t ad, uint64_t bd,
                                           uint32_t idesc, uint32_t en) {
    asm volatile(
        "{\n\t.reg .pred p;\n\tsetp.ne.u32 p, %4, 0;\n\t"
        "tcgen05.mma.cta_group::1.kind::f16 [%0], %1, %2, %3, {%5,%5,%5,%5}, p;\n\t}"
        :: "r"(d), "l"(ad), "l"(bd), "r"(idesc), "r"(en), "r"(0u) : "memory");
}
#define MBAR_INIT(a, c)  asm volatile("mbarrier.init.shared.b64 [%0], %1;" :: "r"(a), "r"(c) : "memory")
#define MBAR_INVAL(a)    asm volatile("mbarrier.inval.shared.b64 [%0];" :: "r"(a) : "memory")
#define TC_COMMIT(a)     asm volatile("tcgen05.commit.cta_group::1.mbarrier::arrive::one.shared::cluster.b64 [%0];" :: "r"(a) : "memory")
#define TC_ALLOC(sa, n)  asm volatile("tcgen05.alloc.cta_group::1.sync.aligned.shared::cta.b32 [%0], %1;" :: "r"(sa), "r"(n) : "memory")
#define TC_DEALLOC(t, n) asm volatile("tcgen05.dealloc.cta_group::1.sync.aligned.b32 %0, %1;" :: "r"(t), "r"(n))
#define TC_RELINQ()      asm volatile("tcgen05.relinquish_alloc_permit.cta_group::1.sync.aligned;")
#define TC_FENCE_AFTER() asm volatile("tcgen05.fence::after_thread_sync;" ::: "memory")
#define TC_WAIT_LD()     asm volatile("tcgen05.wait::ld.sync.aligned;" ::: "memory")
#define FENCE_ASYNC()    asm volatile("fence.proxy.async.shared::cta;" ::: "memory")

__device__ __forceinline__ void mbar_wait(uint32_t mbar, uint32_t parity) {
    asm volatile(
        "{\n\t.reg .pred P;\n\t"
        "W%=:\n\t"
        "mbarrier.try_wait.parity.acquire.cta.shared::cta.b64 P, [%0], %1, 0x989680;\n\t"
        "@P bra.uni D%=;\n\t"
        "bra.uni W%=;\n\t"
        "D%=:\n\t}"
        :: "r"(mbar), "r"(parity) : "memory");
}
__device__ __forceinline__ void cp16(uint32_t saddr, const void* g) {
    asm volatile("cp.async.cg.shared.global [%0], [%1], 16;" :: "r"(saddr), "l"(g) : "memory");
}
#define CP_COMMIT() asm volatile("cp.async.commit_group;" ::: "memory")

__device__ __forceinline__ void ldtm32(uint32_t* r, uint32_t addr) {
    asm volatile(
        "tcgen05.ld.sync.aligned.32x32b.x32.b32 "
        "{%0,%1,%2,%3,%4,%5,%6,%7,%8,%9,%10,%11,%12,%13,%14,%15,"
        "%16,%17,%18,%19,%20,%21,%22,%23,%24,%25,%26,%27,%28,%29,%30,%31}, [%32];"
        : "=r"(r[0]), "=r"(r[1]), "=r"(r[2]), "=r"(r[3]), "=r"(r[4]), "=r"(r[5]), "=r"(r[6]), "=r"(r[7]),
          "=r"(r[8]), "=r"(r[9]), "=r"(r[10]), "=r"(r[11]), "=r"(r[12]), "=r"(r[13]), "=r"(r[14]), "=r"(r[15]),
          "=r"(r[16]), "=r"(r[17]), "=r"(r[18]), "=r"(r[19]), "=r"(r[20]), "=r"(r[21]), "=r"(r[22]), "=r"(r[23]),
          "=r"(r[24]), "=r"(r[25]), "=r"(r[26]), "=r"(r[27]), "=r"(r[28]), "=r"(r[29]), "=r"(r[30]), "=r"(r[31])
        : "r"(addr));
}
#endif

// ================= GEMM + fused gates: grid(4,32) x 256 threads =================
__global__ __launch_bounds__(256, 1)
void lstm_gemm_tc(const float* __restrict__ c, float* __restrict__ out) {
#if HAS_TCGEN05
    extern __shared__ char smem_raw[];
    const uint32_t sbase = smem_u32(smem_raw);
    const int tid  = threadIdx.x;
    const int warp = tid >> 5;
    const int lane = tid & 31;

    const int rowBase = blockIdx.x * BM;
    const int colBase = blockIdx.y * BN;

    if (warp == 0) { TC_ALLOC(sbase + SMEM_TMEM_PTR, 512); }
    else           { TC_RELINQ(); }
    __syncthreads();
    uint32_t tmem_base;
    asm volatile("ld.shared.b32 %0, [%1];" : "=r"(tmem_base) : "r"(sbase + SMEM_TMEM_PTR));

    if (tid == 0) { MBAR_INIT(sbase + SMEM_MBAR0, 1); MBAR_INIT(sbase + SMEM_MBAR1, 1); }
    __syncthreads();

    const __half* Aglob = g_Af16 + (size_t)rowBase * GK;
    const __half* Bglob = g_Wt   + (size_t)colBase * GK;

    #define LOAD_CHUNK(CH) do {                                                        \
        const int kOff = (CH) * BK;                                                    \
        const uint32_t stA = sbase + SMEM_STAGE0 + ((CH) % NSTAGE) * STAGE_BYTES;      \
        const uint32_t stB = stA + STAGE_B_OFF;                                        \
        _Pragma("unroll")                                                              \
        for (int j = 0; j < 8; ++j) {                                                  \
            const int idx = tid + 256 * j;                                             \
            const int row = idx >> 3, kg = idx & 7;                                    \
            const uint32_t so = SW128((uint32_t)(row * 128 + kg * 16));                \
            cp16(stA + so, Aglob + (size_t)row * GK + kOff + kg * 8);                  \
        }                                                                              \
        _Pragma("unroll")                                                              \
        for (int j = 0; j < 8; ++j) {                                                  \
            const int idx = tid + 256 * j;                                             \
            const int row = idx >> 3, kg = idx & 7;                                    \
            const uint32_t so = SW128((uint32_t)(row * 128 + kg * 16));                \
            cp16(stB + so, Bglob + (size_t)row * GK + kOff + kg * 8);                  \
        }                                                                              \
        CP_COMMIT();                                                                   \
    } while (0)

    LOAD_CHUNK(0);
    LOAD_CHUNK(1);

    for (int it = 0; it < NC; ++it) {
        if (it == NC - 1) { asm volatile("cp.async.wait_group 0;" ::: "memory"); }
        else              { asm volatile("cp.async.wait_group 1;" ::: "memory"); }
        __syncthreads();

        if (warp == 0 && elect_one()) {
            FENCE_ASYNC();
            const uint32_t st = sbase + SMEM_STAGE0 + (it % NSTAGE) * STAGE_BYTES;
            const uint64_t aD = MK_DESC(st);
            const uint64_t bD = MK_DESC(st + STAGE_B_OFF);
            #pragma unroll
            for (int m = 0; m < 2; ++m)
                #pragma unroll
                for (int hh = 0; hh < 2; ++hh) {
                    const uint32_t dcol = tmem_base + m * 256 + hh * 128;
                    #pragma unroll
                    for (int ks = 0; ks < 4; ++ks)
                        mma_f16_ss(dcol, aD + m * 1024 + ks * 2, bD + hh * 1024 + ks * 2,
                                   MMA_IDESC, (uint32_t)(it > 0 || ks > 0));
                }
            TC_COMMIT(sbase + ((it & 1) ? SMEM_MBAR1 : SMEM_MBAR0));
        }

        if (it + 2 < NC) {
            if (it >= 1) {
                const int cc = it - 1;
                mbar_wait(sbase + ((cc & 1) ? SMEM_MBAR1 : SMEM_MBAR0), (uint32_t)((cc >> 1) & 1));
            }
            LOAD_CHUNK(it + 2);
        }
    }
    #undef LOAD_CHUNK

    {
        const int cc = NC - 1;
        mbar_wait(sbase + ((cc & 1) ? SMEM_MBAR1 : SMEM_MBAR0), (uint32_t)((cc >> 1) & 1));
    }
    TC_FENCE_AFTER();

    // ---- fused gate epilogue ----
    // warps 0-3 -> M subtile 0 (D cols 0..255), warps 4-7 -> M subtile 1.
    // Within a 32-col block: cols 4j..4j+3 = (i,f,g,o) for unit uu = uuBase + cb*8 + j.
    {
        const int m   = warp >> 2;
        const int sub = warp & 3;
        const int b   = rowBase + m * 128 + sub * 32 + lane;   // batch row
        const int nsp    = colBase >> 12;
        const int uuBase = (colBase & 4095) >> 2;
        const float* cRow = c + (size_t)b * UU;
        float* outH = out + (size_t)b * UU;
        float* outC = out + (size_t)BB * UU + (size_t)b * UU;

        uint32_t regs[32];
        #pragma unroll
        for (int cb = 0; cb < 8; ++cb) {
            ldtm32(regs, tmem_base + m * 256 + cb * 32);
            TC_WAIT_LD();
            const int u0 = nsp * 1024 + uuBase + cb * 8;
            float cArr[8], hArr[8], nArr[8];
            *reinterpret_cast<float4*>(&cArr[0]) = *reinterpret_cast<const float4*>(cRow + u0);
            *reinterpret_cast<float4*>(&cArr[4]) = *reinterpret_cast<const float4*>(cRow + u0 + 4);
            #pragma unroll
            for (int j = 0; j < 8; ++j) {
                const float iv = __uint_as_float(regs[4 * j + 0]);
                const float fv = __uint_as_float(regs[4 * j + 1]);
                const float gv = __uint_as_float(regs[4 * j + 2]);
                const float ov = __uint_as_float(regs[4 * j + 3]);
                const float ig = sigmoidf_(iv);
                const float fg = sigmoidf_(fv);
                const float og = sigmoidf_(ov);
                const float gg = tanhf(gv);
                const float nc = fg * cArr[j] + ig * gg;
                nArr[j] = nc;
                hArr[j] = og * tanhf(nc);
            }
            *reinterpret_cast<float4*>(outH + u0)     = *reinterpret_cast<float4*>(&hArr[0]);
            *reinterpret_cast<float4*>(outH + u0 + 4) = *reinterpret_cast<float4*>(&hArr[4]);
            *reinterpret_cast<float4*>(outC + u0)     = *reinterpret_cast<float4*>(&nArr[0]);
            *reinterpret_cast<float4*>(outC + u0 + 4) = *reinterpret_cast<float4*>(&nArr[4]);
        }
    }

    __syncthreads();
    if (tid == 0) { MBAR_INVAL(sbase + SMEM_MBAR0); MBAR_INVAL(sbase + SMEM_MBAR1); }
    __syncthreads();
    if (warp == 0) { TC_DEALLOC(tmem_base, 512); }

#else
    // ===== baseline-arch fallback (compile-correct; never selected on sm_103a) =====
    // Consumes the SAME permuted g_Wt / g_Af16 and writes fused gates directly.
    const int tid = threadIdx.x;
    const int rowBase = blockIdx.x * BM;
    const int colBase = blockIdx.y * BN;
    const int nsp    = colBase >> 12;
    const int uuBase = (colBase & 4095) >> 2;
    const int b = rowBase + tid;                 // one batch row per thread
    const __half* arow = g_Af16 + (size_t)b * GK;
    for (int j = 0; j < 64; ++j) {
        const __half* brow = g_Wt + (size_t)(colBase + j * 4) * GK;
        float acc[4] = {0.f, 0.f, 0.f, 0.f};
        for (int k = 0; k < GK; ++k) {
            const float a = __half2float(arow[k]);
            acc[0] += a * __half2float(brow[k]);
            acc[1] += a * __half2float(brow[(size_t)GK + k]);
            acc[2] += a * __half2float(brow[(size_t)2 * GK + k]);
            acc[3] += a * __half2float(brow[(size_t)3 * GK + k]);
        }
        const int u = nsp * 1024 + uuBase + j;
        const float ig = sigmoidf_(acc[0]);
        const float fg = sigmoidf_(acc[1]);
        const float gg = tanhf(acc[2]);
        const float og = sigmoidf_(acc[3]);
        const float cin = c[(size_t)b * UU + u];
        const float nc = fg * cin + ig * gg;
        out[(size_t)b * UU + u] = og * tanhf(nc);
        out[(size_t)BB * UU + (size_t)b * UU + u] = nc;
    }
#endif
}

// ================= launch =================
extern "C" void kernel_launch(void* const* d_in, const int* in_sizes, int n_in,
                              void* d_out, int out_size) {
    const float* x = (const float*)d_in[0];
    const float* h = (const float*)d_in[1];
    const float* c = (const float*)d_in[2];
    const float* W = (const float*)d_in[3];
    float* out = (float*)d_out;

    cudaFuncSetAttribute(lstm_gemm_tc, cudaFuncAttributeMaxDynamicSharedMemorySize, SMEM_BYTES);

    pack_a_kernel<<<(BB * GK / 4) / 256, 256>>>(x, h);
    transpose_w_kernel<<<dim3(4096 / 32, 2048 / 32, 4), dim3(32, 8)>>>(W);
    lstm_gemm_tc<<<dim3(4, 32), 256, SMEM_BYTES>>>(c, out);
}